// round 11
// baseline (speedup 1.0000x reference)
#include <cuda_runtime.h>
#include <math.h>
#include <stdint.h>

#define RR 3
#define NN 100000
#define EE 400000
#define INDIM 128
#define HDIM 128
#define NH 8
#define DD 16
#define NEG_SLOPE 0.2f

// d_out layout: out (R*N*HD) | rel_out (R*64) | dst_after (R*N*HD)
#define RELOUT_OFF (RR*NN*HDIM)
#define DSTAFTER_OFF (RR*NN*HDIM + RR*64)

// -------- scratch (static device arrays; no runtime allocation) --------
__device__ float g_fs[RR * NN * HDIM];     // relation-specific src features
__device__ float g_es[RR * NN * NH];       // per-node src attention logits
__device__ float g_ed[RR * NN * NH];       // per-node dst attention logits
__device__ float g_rw[RR * 256];           // rel attention vectors (H x 2D)
__device__ float g_Wnr[RR * HDIM * HDIM];  // Wn @ Wr[r]
__device__ float g_bnr[RR * HDIM];         // bn @ Wr[r] + br[r]
__device__ int   g_cnt[RR * NN];
__device__ int   g_off[RR * (NN + 1)];
__device__ int   g_cur[RR * NN];
__device__ int   g_eix[RR * EE];

// ======================= prep: tiny GEMMs =======================
__global__ void prep_kernel(const float* __restrict__ rel_emb,
                            const float* __restrict__ Wn, const float* __restrict__ bn,
                            const float* __restrict__ Wr, const float* __restrict__ br,
                            const float* __restrict__ rel_attn_w,
                            const float* __restrict__ Wp, const float* __restrict__ bp,
                            float* __restrict__ rel_out)
{
    int r = blockIdx.y;
    int t = threadIdx.x;
    if (blockIdx.x < 8) {
        // Wnr[r] rows [bx*16, bx*16+16)
        #pragma unroll 1
        for (int o = 0; o < 8; o++) {
            int lin = o * 256 + t;
            int i = blockIdx.x * 16 + (lin >> 7);
            int j = lin & 127;
            float s = 0.f;
            const float* wn_row = Wn + i * 128;
            const float* wr_col = Wr + r * 16384 + j;
            #pragma unroll 8
            for (int k = 0; k < 128; k++) s = fmaf(wn_row[k], wr_col[k * 128], s);
            g_Wnr[r * 16384 + i * 128 + j] = s;
        }
    } else {
        // rw[r] = rel_emb[r] @ rel_attn_w[r]  -> 256 values
        {
            float s = 0.f;
            const float* a = rel_attn_w + r * 16384 + t;   // (64,256) col t
            const float* e = rel_emb + r * 64;
            #pragma unroll 8
            for (int k = 0; k < 64; k++) s = fmaf(e[k], a[k * 256], s);
            g_rw[r * 256 + t] = s;
        }
        if (t < 128) {
            float s = br[r * 128 + t];
            const float* wr_col = Wr + r * 16384 + t;
            #pragma unroll 8
            for (int k = 0; k < 128; k++) s = fmaf(bn[k], wr_col[k * 128], s);
            g_bnr[r * 128 + t] = s;
        }
        if (t < 64) {
            float s = bp[r * 64 + t];
            const float* wp_col = Wp + r * 4096 + t;
            #pragma unroll 8
            for (int k = 0; k < 64; k++) s = fmaf(rel_emb[r * 64 + k], wp_col[k * 64], s);
            rel_out[r * 64 + t] = s;
        }
    }
}

// ======================= fused triple GEMM =======================
// Per CTA: 128-row x tile; phases: f=x@Wn (+e_dst reduce), fs=x@Wnr (+e_src reduce), res=x@Wres.
#define SMEM_FLOATS (128*129 + 128*128 + 1024)

__global__ void __launch_bounds__(256, 1) gemm_kernel(
    const float* __restrict__ x,
    const float* __restrict__ Wn, const float* __restrict__ bn,
    const float* __restrict__ Wres, const float* __restrict__ bres,
    float* __restrict__ dout)
{
    extern __shared__ float sm[];
    float* xs = sm;                    // [k][m], stride 129
    float* ws = sm + 128 * 129;        // [k][n], stride 128
    float* red = ws + 128 * 128;       // [m][h] head-reduction, 128*8

    int r = blockIdx.y;
    int m0 = blockIdx.x * 128;
    int rows = NN - m0; if (rows > 128) rows = 128;
    int t = threadIdx.x;
    int tx = t & 15, ty = t >> 4;

    // load x tile transposed into smem
    const float* xr = x + (size_t)(r * NN + m0) * 128;
    #pragma unroll
    for (int i = 0; i < 16; i++) {
        int idx = i * 256 + t;
        int row = idx >> 5, kc = idx & 31;
        float4 v = make_float4(0.f, 0.f, 0.f, 0.f);
        if (row < rows) v = *(const float4*)(xr + row * 128 + kc * 4);
        int b = (kc * 4) * 129 + row;
        xs[b] = v.x; xs[b + 129] = v.y; xs[b + 258] = v.z; xs[b + 387] = v.w;
    }

    for (int p = 0; p < 3; p++) {
        const float* W; const float* bias; float* dest; int coefOff;
        if (p == 0)      { W = Wn;                  bias = bn;              dest = dout + DSTAFTER_OFF; coefOff = 0;  }
        else if (p == 1) { W = g_Wnr + r * 16384;   bias = g_bnr + r * 128; dest = g_fs;                coefOff = 16; }
        else             { W = Wres;                bias = bres;            dest = dout;                coefOff = -1; }

        __syncthreads();   // prev phase fully done with ws/red; xs ready on p==0
        if (p < 2) {
            #pragma unroll
            for (int i = 0; i < 4; i++) red[i * 256 + t] = 0.f;
        }
        #pragma unroll
        for (int i = 0; i < 16; i++) {
            int idx = i * 256 + t;
            ((float4*)ws)[idx] = ((const float4*)W)[idx];
        }
        __syncthreads();

        float acc[8][8];
        #pragma unroll
        for (int i = 0; i < 8; i++)
            #pragma unroll
            for (int j = 0; j < 8; j++) acc[i][j] = 0.f;

        #pragma unroll 4
        for (int k = 0; k < 128; k++) {
            float av[8], bv[8];
            #pragma unroll
            for (int i = 0; i < 4; i++) {
                av[i]     = xs[k * 129 + ty * 4 + i];
                av[4 + i] = xs[k * 129 + 64 + ty * 4 + i];
            }
            float4 b0 = *(const float4*)(ws + k * 128 + tx * 4);
            float4 b1 = *(const float4*)(ws + k * 128 + 64 + tx * 4);
            bv[0]=b0.x; bv[1]=b0.y; bv[2]=b0.z; bv[3]=b0.w;
            bv[4]=b1.x; bv[5]=b1.y; bv[6]=b1.z; bv[7]=b1.w;
            #pragma unroll
            for (int i = 0; i < 8; i++)
                #pragma unroll
                for (int j = 0; j < 8; j++)
                    acc[i][j] = fmaf(av[i], bv[j], acc[i][j]);
        }

        // epilogue
        float bb[8];
        #pragma unroll
        for (int j = 0; j < 4; j++) {
            bb[j]     = bias[tx * 4 + j];
            bb[4 + j] = bias[64 + tx * 4 + j];
        }
        float cf[8];
        if (p < 2) {
            #pragma unroll
            for (int j = 0; j < 4; j++) {
                int c  = tx * 4 + j;
                int c2 = 64 + tx * 4 + j;
                cf[j]     = g_rw[r * 256 + (c  >> 4) * 32 + coefOff + (c  & 15)];
                cf[4 + j] = g_rw[r * 256 + (c2 >> 4) * 32 + coefOff + (c2 & 15)];
            }
        }
        int h0 = tx >> 2, h1 = 4 + (tx >> 2);
        #pragma unroll
        for (int mi = 0; mi < 8; mi++) {
            int row = ty * 4 + (mi & 3) + ((mi >> 2) << 6);
            if (row < rows) {
                float v[8];
                #pragma unroll
                for (int j = 0; j < 8; j++) v[j] = acc[mi][j] + bb[j];
                float* dp = dest + (size_t)(r * NN + m0 + row) * 128 + tx * 4;
                *(float4*)dp        = make_float4(v[0], v[1], v[2], v[3]);
                *(float4*)(dp + 64) = make_float4(v[4], v[5], v[6], v[7]);
                if (p < 2) {
                    float p0 = v[0]*cf[0] + v[1]*cf[1] + v[2]*cf[2] + v[3]*cf[3];
                    float p1 = v[4]*cf[4] + v[5]*cf[5] + v[6]*cf[6] + v[7]*cf[7];
                    atomicAdd(&red[row * 8 + h0], p0);
                    atomicAdd(&red[row * 8 + h1], p1);
                }
            }
        }
        if (p < 2) {
            __syncthreads();
            float* eg = (p == 0) ? g_ed : g_es;
            #pragma unroll
            for (int i = 0; i < 4; i++) {
                int idx = i * 256 + t;
                int row = idx >> 3, h = idx & 7;
                if (row < rows) eg[(size_t)(r * NN + m0 + row) * 8 + h] = red[idx];
            }
        }
    }
}

// ======================= CSR build =======================
__global__ void zero_cnt_kernel() {
    int i = blockIdx.x * blockDim.x + threadIdx.x;
    if (i < RR * NN) g_cnt[i] = 0;
}

__global__ void hist_kernel(const int* __restrict__ dst) {
    int g = blockIdx.x * blockDim.x + threadIdx.x;
    if (g < RR * EE) {
        int r = g / EE;
        atomicAdd(&g_cnt[r * NN + dst[g]], 1);
    }
}

__global__ void scan_kernel() {
    int r = blockIdx.x;
    const int4* cnt4 = (const int4*)(g_cnt + r * NN);
    int* off = g_off + r * (NN + 1);
    int* cur = g_cur + r * NN;
    __shared__ int wsum[32];
    __shared__ int carry_s;
    int t = threadIdx.x, lane = t & 31, w = t >> 5;
    if (t == 0) carry_s = 0;
    __syncthreads();
    const int CH = 1024 * 4;
    for (int base = 0; base < NN; base += CH) {
        int i4 = (base >> 2) + t;
        int4 v = (i4 < NN / 4) ? cnt4[i4] : make_int4(0, 0, 0, 0);
        int sum = v.x + v.y + v.z + v.w;
        int s = sum;
        #pragma unroll
        for (int d = 1; d < 32; d <<= 1) {
            int u = __shfl_up_sync(0xffffffffu, s, d);
            if (lane >= d) s += u;
        }
        if (lane == 31) wsum[w] = s;
        __syncthreads();
        if (w == 0) {
            int ws2 = wsum[lane];
            #pragma unroll
            for (int d = 1; d < 32; d <<= 1) {
                int u = __shfl_up_sync(0xffffffffu, ws2, d);
                if (lane >= d) ws2 += u;
            }
            wsum[lane] = ws2;
        }
        __syncthreads();
        int excl = carry_s + (w ? wsum[w - 1] : 0) + s - sum;
        int i = i4 * 4;
        if (i < NN) {
            int e0 = excl, e1 = excl + v.x, e2 = e1 + v.y, e3 = e2 + v.z;
            off[i] = e0;     cur[i] = e0;
            off[i + 1] = e1; cur[i + 1] = e1;
            off[i + 2] = e2; cur[i + 2] = e2;
            off[i + 3] = e3; cur[i + 3] = e3;
        }
        __syncthreads();
        if (t == 0) carry_s += wsum[31];
        __syncthreads();
    }
    if (t == 0) off[NN] = carry_s;
}

__global__ void scatter_kernel(const int* __restrict__ dst) {
    int g = blockIdx.x * blockDim.x + threadIdx.x;
    if (g < RR * EE) {
        int r = g / EE;
        int e = g - r * EE;
        int pos = atomicAdd(&g_cur[r * NN + dst[g]], 1);
        g_eix[r * EE + pos] = e;
    }
}

// ============ aggregation + residual gate + cross-relation attention ============
// One warp per node. Lane l owns dims [4l, 4l+4) => head l>>2.
__global__ void __launch_bounds__(256) agg_cross_kernel(
    const int* __restrict__ src, const float* __restrict__ res_w,
    const float* __restrict__ cross_w, float* __restrict__ dout)
{
    int wg = (blockIdx.x * 256 + threadIdx.x) >> 5;
    if (wg >= NN) return;
    int n = wg;
    int lane = threadIdx.x & 31;
    int h = lane >> 2;
    float alpha = 1.f / (1.f + __expf(-res_w[0]));
    float om = 1.f - alpha;

    float4 feat[3];
    #pragma unroll 1
    for (int r = 0; r < RR; r++) {
        int beg = g_off[r * (NN + 1) + n];
        int end = g_off[r * (NN + 1) + n + 1];
        float edst = g_ed[(size_t)(r * NN + n) * 8 + h];

        float m = -1e30f;
        for (int i = beg; i < end; i++) {
            int e = g_eix[r * EE + i];
            int s2 = src[r * EE + e];
            float ev = g_es[(size_t)(r * NN + s2) * 8 + h] + edst;
            ev = ev > 0.f ? ev : NEG_SLOPE * ev;
            m = fmaxf(m, ev);
        }
        float4 acc = make_float4(0.f, 0.f, 0.f, 0.f);
        float z = 0.f;
        for (int i = beg; i < end; i++) {
            int e = g_eix[r * EE + i];
            int s2 = src[r * EE + e];
            float ev = g_es[(size_t)(r * NN + s2) * 8 + h] + edst;
            ev = ev > 0.f ? ev : NEG_SLOPE * ev;
            float a = __expf(ev - m);
            z += a;
            float4 v = *(const float4*)(g_fs + (size_t)(r * NN + s2) * 128 + lane * 4);
            acc.x = fmaf(a, v.x, acc.x);
            acc.y = fmaf(a, v.y, acc.y);
            acc.z = fmaf(a, v.z, acc.z);
            acc.w = fmaf(a, v.w, acc.w);
        }
        float inv = 1.f / (z + 1e-16f);
        float4 rr = *(const float4*)(dout + (size_t)(r * NN + n) * 128 + lane * 4); // res staged here
        feat[r].x = fmaxf(acc.x * inv, 0.f) * alpha + rr.x * om;
        feat[r].y = fmaxf(acc.y * inv, 0.f) * alpha + rr.y * om;
        feat[r].z = fmaxf(acc.z * inv, 0.f) * alpha + rr.z * om;
        feat[r].w = fmaxf(acc.w * inv, 0.f) * alpha + rr.w * om;
    }

    // cross-relation attention
    float4 cwv[3];
    #pragma unroll
    for (int e = 0; e < 3; e++) cwv[e] = ((const float4*)cross_w)[e * 32 + lane];

    float sc[3][3];
    #pragma unroll
    for (int e = 0; e < 3; e++) {
        #pragma unroll
        for (int r = 0; r < 3; r++) {
            float p = feat[r].x * cwv[e].x + feat[r].y * cwv[e].y
                    + feat[r].z * cwv[e].z + feat[r].w * cwv[e].w;
            p += __shfl_xor_sync(0xffffffffu, p, 1);
            p += __shfl_xor_sync(0xffffffffu, p, 2);
            sc[e][r] = p > 0.f ? p : NEG_SLOPE * p;
        }
    }
    #pragma unroll
    for (int e = 0; e < 3; e++) {
        float mm = fmaxf(sc[e][0], fmaxf(sc[e][1], sc[e][2]));
        float x0 = __expf(sc[e][0] - mm);
        float x1 = __expf(sc[e][1] - mm);
        float x2 = __expf(sc[e][2] - mm);
        float inv = 1.f / (x0 + x1 + x2);
        float a0 = x0 * inv, a1 = x1 * inv, a2 = x2 * inv;
        float4 o;
        o.x = a0 * feat[0].x + a1 * feat[1].x + a2 * feat[2].x;
        o.y = a0 * feat[0].y + a1 * feat[1].y + a2 * feat[2].y;
        o.z = a0 * feat[0].z + a1 * feat[1].z + a2 * feat[2].z;
        o.w = a0 * feat[0].w + a1 * feat[1].w + a2 * feat[2].w;
        *(float4*)(dout + (size_t)(e * NN + n) * 128 + lane * 4) = o;
    }
}

// ======================= launch =======================
extern "C" void kernel_launch(void* const* d_in, const int* in_sizes, int n_in,
                              void* d_out, int out_size)
{
    const float* x          = (const float*)d_in[0];
    const float* rel_emb    = (const float*)d_in[1];
    const int*   src        = (const int*)d_in[2];
    const int*   dst        = (const int*)d_in[3];
    const float* Wn         = (const float*)d_in[4];
    const float* bn         = (const float*)d_in[5];
    const float* Wr         = (const float*)d_in[6];
    const float* br         = (const float*)d_in[7];
    const float* rel_attn_w = (const float*)d_in[8];
    const float* Wp         = (const float*)d_in[9];
    const float* bp         = (const float*)d_in[10];
    const float* Wres       = (const float*)d_in[11];
    const float* bres       = (const float*)d_in[12];
    const float* res_w      = (const float*)d_in[13];
    const float* cross_w    = (const float*)d_in[14];
    float* out = (float*)d_out;

    const int smem_bytes = SMEM_FLOATS * sizeof(float);
    cudaFuncSetAttribute(gemm_kernel, cudaFuncAttributeMaxDynamicSharedMemorySize, smem_bytes);

    prep_kernel<<<dim3(9, 3), 256>>>(rel_emb, Wn, bn, Wr, br, rel_attn_w, Wp, bp,
                                     out + RELOUT_OFF);
    zero_cnt_kernel<<<(RR * NN + 255) / 256, 256>>>();
    hist_kernel<<<(RR * EE + 255) / 256, 256>>>(dst);
    scan_kernel<<<3, 1024>>>();
    scatter_kernel<<<(RR * EE + 255) / 256, 256>>>(dst);
    gemm_kernel<<<dim3((NN + 127) / 128, 3), 256, smem_bytes>>>(x, Wn, bn, Wres, bres, out);
    agg_cross_kernel<<<(NN + 7) / 8, 256>>>(src, res_w, cross_w, out);
}

// round 12
// speedup vs baseline: 1.0054x; 1.0054x over previous
#include <cuda_runtime.h>
#include <math.h>
#include <stdint.h>

#define RR 3
#define NN 100000
#define EE 400000
#define INDIM 128
#define HDIM 128
#define NH 8
#define DD 16
#define NEG_SLOPE 0.2f

// d_out layout: out (R*N*HD) | rel_out (R*64) | dst_after (R*N*HD)
#define RELOUT_OFF (RR*NN*HDIM)
#define DSTAFTER_OFF (RR*NN*HDIM + RR*64)

// -------- scratch (static device arrays; no runtime allocation) --------
__device__ float g_fs[RR * NN * HDIM];     // relation-specific src features
__device__ float g_es[RR * NN * NH];       // per-node src attention logits
__device__ float g_ed[RR * NN * NH];       // per-node dst attention logits
__device__ float g_rw[RR * 256];           // rel attention vectors (H x 2D)
__device__ float g_Wnr[RR * HDIM * HDIM];  // Wn @ Wr[r]
__device__ float g_bnr[RR * HDIM];         // bn @ Wr[r] + br[r]
__device__ int   g_cnt[RR * NN];
__device__ int   g_off[RR * (NN + 1)];
__device__ int   g_cur[RR * NN];
__device__ int   g_eix[RR * EE];

// ======================= prep: tiny GEMMs =======================
__global__ void prep_kernel(const float* __restrict__ rel_emb,
                            const float* __restrict__ Wn, const float* __restrict__ bn,
                            const float* __restrict__ Wr, const float* __restrict__ br,
                            const float* __restrict__ rel_attn_w,
                            const float* __restrict__ Wp, const float* __restrict__ bp,
                            float* __restrict__ rel_out)
{
    int r = blockIdx.y;
    int t = threadIdx.x;
    if (blockIdx.x < 8) {
        // Wnr[r] rows [bx*16, bx*16+16)
        #pragma unroll 1
        for (int o = 0; o < 8; o++) {
            int lin = o * 256 + t;
            int i = blockIdx.x * 16 + (lin >> 7);
            int j = lin & 127;
            float s = 0.f;
            const float* wn_row = Wn + i * 128;
            const float* wr_col = Wr + r * 16384 + j;
            #pragma unroll 8
            for (int k = 0; k < 128; k++) s = fmaf(wn_row[k], wr_col[k * 128], s);
            g_Wnr[r * 16384 + i * 128 + j] = s;
        }
    } else {
        // rw[r] = rel_emb[r] @ rel_attn_w[r]  -> 256 values
        {
            float s = 0.f;
            const float* a = rel_attn_w + r * 16384 + t;   // (64,256) col t
            const float* e = rel_emb + r * 64;
            #pragma unroll 8
            for (int k = 0; k < 64; k++) s = fmaf(e[k], a[k * 256], s);
            g_rw[r * 256 + t] = s;
        }
        if (t < 128) {
            float s = br[r * 128 + t];
            const float* wr_col = Wr + r * 16384 + t;
            #pragma unroll 8
            for (int k = 0; k < 128; k++) s = fmaf(bn[k], wr_col[k * 128], s);
            g_bnr[r * 128 + t] = s;
        }
        if (t < 64) {
            float s = bp[r * 64 + t];
            const float* wp_col = Wp + r * 4096 + t;
            #pragma unroll 8
            for (int k = 0; k < 64; k++) s = fmaf(rel_emb[r * 64 + k], wp_col[k * 64], s);
            rel_out[r * 64 + t] = s;
        }
    }
}

// ======================= fused triple GEMM =======================
// Per CTA: 128-row x tile; phases: f=x@Wn (+e_dst reduce), fs=x@Wnr (+e_src reduce), res=x@Wres.
#define SMEM_FLOATS (128*129 + 128*128 + 1024)

__global__ void __launch_bounds__(256, 1) gemm_kernel(
    const float* __restrict__ x,
    const float* __restrict__ Wn, const float* __restrict__ bn,
    const float* __restrict__ Wres, const float* __restrict__ bres,
    float* __restrict__ dout)
{
    extern __shared__ float sm[];
    float* xs = sm;                    // [k][m], stride 129
    float* ws = sm + 128 * 129;        // [k][n], stride 128
    float* red = ws + 128 * 128;       // [m][h] head-reduction, 128*8

    int r = blockIdx.y;
    int m0 = blockIdx.x * 128;
    int rows = NN - m0; if (rows > 128) rows = 128;
    int t = threadIdx.x;
    int tx = t & 15, ty = t >> 4;

    // load x tile transposed into smem
    const float* xr = x + (size_t)(r * NN + m0) * 128;
    #pragma unroll
    for (int i = 0; i < 16; i++) {
        int idx = i * 256 + t;
        int row = idx >> 5, kc = idx & 31;
        float4 v = make_float4(0.f, 0.f, 0.f, 0.f);
        if (row < rows) v = *(const float4*)(xr + row * 128 + kc * 4);
        int b = (kc * 4) * 129 + row;
        xs[b] = v.x; xs[b + 129] = v.y; xs[b + 258] = v.z; xs[b + 387] = v.w;
    }

    for (int p = 0; p < 3; p++) {
        const float* W; const float* bias; float* dest; int coefOff;
        if (p == 0)      { W = Wn;                  bias = bn;              dest = dout + DSTAFTER_OFF; coefOff = 0;  }
        else if (p == 1) { W = g_Wnr + r * 16384;   bias = g_bnr + r * 128; dest = g_fs;                coefOff = 16; }
        else             { W = Wres;                bias = bres;            dest = dout;                coefOff = -1; }

        __syncthreads();   // prev phase fully done with ws/red; xs ready on p==0
        if (p < 2) {
            #pragma unroll
            for (int i = 0; i < 4; i++) red[i * 256 + t] = 0.f;
        }
        #pragma unroll
        for (int i = 0; i < 16; i++) {
            int idx = i * 256 + t;
            ((float4*)ws)[idx] = ((const float4*)W)[idx];
        }
        __syncthreads();

        float acc[8][8];
        #pragma unroll
        for (int i = 0; i < 8; i++)
            #pragma unroll
            for (int j = 0; j < 8; j++) acc[i][j] = 0.f;

        #pragma unroll 4
        for (int k = 0; k < 128; k++) {
            float av[8], bv[8];
            #pragma unroll
            for (int i = 0; i < 4; i++) {
                av[i]     = xs[k * 129 + ty * 4 + i];
                av[4 + i] = xs[k * 129 + 64 + ty * 4 + i];
            }
            float4 b0 = *(const float4*)(ws + k * 128 + tx * 4);
            float4 b1 = *(const float4*)(ws + k * 128 + 64 + tx * 4);
            bv[0]=b0.x; bv[1]=b0.y; bv[2]=b0.z; bv[3]=b0.w;
            bv[4]=b1.x; bv[5]=b1.y; bv[6]=b1.z; bv[7]=b1.w;
            #pragma unroll
            for (int i = 0; i < 8; i++)
                #pragma unroll
                for (int j = 0; j < 8; j++)
                    acc[i][j] = fmaf(av[i], bv[j], acc[i][j]);
        }

        // epilogue
        float bb[8];
        #pragma unroll
        for (int j = 0; j < 4; j++) {
            bb[j]     = bias[tx * 4 + j];
            bb[4 + j] = bias[64 + tx * 4 + j];
        }
        float cf[8];
        if (p < 2) {
            #pragma unroll
            for (int j = 0; j < 4; j++) {
                int c  = tx * 4 + j;
                int c2 = 64 + tx * 4 + j;
                cf[j]     = g_rw[r * 256 + (c  >> 4) * 32 + coefOff + (c  & 15)];
                cf[4 + j] = g_rw[r * 256 + (c2 >> 4) * 32 + coefOff + (c2 & 15)];
            }
        }
        int h0 = tx >> 2, h1 = 4 + (tx >> 2);
        #pragma unroll
        for (int mi = 0; mi < 8; mi++) {
            int row = ty * 4 + (mi & 3) + ((mi >> 2) << 6);
            if (row < rows) {
                float v[8];
                #pragma unroll
                for (int j = 0; j < 8; j++) v[j] = acc[mi][j] + bb[j];
                float* dp = dest + (size_t)(r * NN + m0 + row) * 128 + tx * 4;
                *(float4*)dp        = make_float4(v[0], v[1], v[2], v[3]);
                *(float4*)(dp + 64) = make_float4(v[4], v[5], v[6], v[7]);
                if (p < 2) {
                    float p0 = v[0]*cf[0] + v[1]*cf[1] + v[2]*cf[2] + v[3]*cf[3];
                    float p1 = v[4]*cf[4] + v[5]*cf[5] + v[6]*cf[6] + v[7]*cf[7];
                    atomicAdd(&red[row * 8 + h0], p0);
                    atomicAdd(&red[row * 8 + h1], p1);
                }
            }
        }
        if (p < 2) {
            __syncthreads();
            float* eg = (p == 0) ? g_ed : g_es;
            #pragma unroll
            for (int i = 0; i < 4; i++) {
                int idx = i * 256 + t;
                int row = idx >> 3, h = idx & 7;
                if (row < rows) eg[(size_t)(r * NN + m0 + row) * 8 + h] = red[idx];
            }
        }
    }
}

// ======================= CSR build =======================
__global__ void zero_cnt_kernel() {
    int i = blockIdx.x * blockDim.x + threadIdx.x;
    if (i < RR * NN) g_cnt[i] = 0;
}

__global__ void hist_kernel(const int* __restrict__ dst) {
    int g = blockIdx.x * blockDim.x + threadIdx.x;
    if (g < RR * EE) {
        int r = g / EE;
        atomicAdd(&g_cnt[r * NN + dst[g]], 1);
    }
}

__global__ void scan_kernel() {
    int r = blockIdx.x;
    const int4* cnt4 = (const int4*)(g_cnt + r * NN);
    int* off = g_off + r * (NN + 1);
    int* cur = g_cur + r * NN;
    __shared__ int wsum[32];
    __shared__ int carry_s;
    int t = threadIdx.x, lane = t & 31, w = t >> 5;
    if (t == 0) carry_s = 0;
    __syncthreads();
    const int CH = 1024 * 4;
    for (int base = 0; base < NN; base += CH) {
        int i4 = (base >> 2) + t;
        int4 v = (i4 < NN / 4) ? cnt4[i4] : make_int4(0, 0, 0, 0);
        int sum = v.x + v.y + v.z + v.w;
        int s = sum;
        #pragma unroll
        for (int d = 1; d < 32; d <<= 1) {
            int u = __shfl_up_sync(0xffffffffu, s, d);
            if (lane >= d) s += u;
        }
        if (lane == 31) wsum[w] = s;
        __syncthreads();
        if (w == 0) {
            int ws2 = wsum[lane];
            #pragma unroll
            for (int d = 1; d < 32; d <<= 1) {
                int u = __shfl_up_sync(0xffffffffu, ws2, d);
                if (lane >= d) ws2 += u;
            }
            wsum[lane] = ws2;
        }
        __syncthreads();
        int excl = carry_s + (w ? wsum[w - 1] : 0) + s - sum;
        int i = i4 * 4;
        if (i < NN) {
            int e0 = excl, e1 = excl + v.x, e2 = e1 + v.y, e3 = e2 + v.z;
            off[i] = e0;     cur[i] = e0;
            off[i + 1] = e1; cur[i + 1] = e1;
            off[i + 2] = e2; cur[i + 2] = e2;
            off[i + 3] = e3; cur[i + 3] = e3;
        }
        __syncthreads();
        if (t == 0) carry_s += wsum[31];
        __syncthreads();
    }
    if (t == 0) off[NN] = carry_s;
}

__global__ void scatter_kernel(const int* __restrict__ dst) {
    int g = blockIdx.x * blockDim.x + threadIdx.x;
    if (g < RR * EE) {
        int r = g / EE;
        int e = g - r * EE;
        int pos = atomicAdd(&g_cur[r * NN + dst[g]], 1);
        g_eix[r * EE + pos] = e;
    }
}

// ============ aggregation + residual gate + cross-relation attention ============
// One warp per node. Lane l owns dims [4l, 4l+4) => head l>>2.
__global__ void __launch_bounds__(256) agg_cross_kernel(
    const int* __restrict__ src, const float* __restrict__ res_w,
    const float* __restrict__ cross_w, float* __restrict__ dout)
{
    int wg = (blockIdx.x * 256 + threadIdx.x) >> 5;
    if (wg >= NN) return;
    int n = wg;
    int lane = threadIdx.x & 31;
    int h = lane >> 2;
    float alpha = 1.f / (1.f + __expf(-res_w[0]));
    float om = 1.f - alpha;

    float4 feat[3];
    #pragma unroll 1
    for (int r = 0; r < RR; r++) {
        int beg = g_off[r * (NN + 1) + n];
        int end = g_off[r * (NN + 1) + n + 1];
        float edst = g_ed[(size_t)(r * NN + n) * 8 + h];

        float m = -1e30f;
        for (int i = beg; i < end; i++) {
            int e = g_eix[r * EE + i];
            int s2 = src[r * EE + e];
            float ev = g_es[(size_t)(r * NN + s2) * 8 + h] + edst;
            ev = ev > 0.f ? ev : NEG_SLOPE * ev;
            m = fmaxf(m, ev);
        }
        float4 acc = make_float4(0.f, 0.f, 0.f, 0.f);
        float z = 0.f;
        for (int i = beg; i < end; i++) {
            int e = g_eix[r * EE + i];
            int s2 = src[r * EE + e];
            float ev = g_es[(size_t)(r * NN + s2) * 8 + h] + edst;
            ev = ev > 0.f ? ev : NEG_SLOPE * ev;
            float a = __expf(ev - m);
            z += a;
            float4 v = *(const float4*)(g_fs + (size_t)(r * NN + s2) * 128 + lane * 4);
            acc.x = fmaf(a, v.x, acc.x);
            acc.y = fmaf(a, v.y, acc.y);
            acc.z = fmaf(a, v.z, acc.z);
            acc.w = fmaf(a, v.w, acc.w);
        }
        float inv = 1.f / (z + 1e-16f);
        float4 rr = *(const float4*)(dout + (size_t)(r * NN + n) * 128 + lane * 4); // res staged here
        feat[r].x = fmaxf(acc.x * inv, 0.f) * alpha + rr.x * om;
        feat[r].y = fmaxf(acc.y * inv, 0.f) * alpha + rr.y * om;
        feat[r].z = fmaxf(acc.z * inv, 0.f) * alpha + rr.z * om;
        feat[r].w = fmaxf(acc.w * inv, 0.f) * alpha + rr.w * om;
    }

    // cross-relation attention
    float4 cwv[3];
    #pragma unroll
    for (int e = 0; e < 3; e++) cwv[e] = ((const float4*)cross_w)[e * 32 + lane];

    float sc[3][3];
    #pragma unroll
    for (int e = 0; e < 3; e++) {
        #pragma unroll
        for (int r = 0; r < 3; r++) {
            float p = feat[r].x * cwv[e].x + feat[r].y * cwv[e].y
                    + feat[r].z * cwv[e].z + feat[r].w * cwv[e].w;
            p += __shfl_xor_sync(0xffffffffu, p, 1);
            p += __shfl_xor_sync(0xffffffffu, p, 2);
            sc[e][r] = p > 0.f ? p : NEG_SLOPE * p;
        }
    }
    #pragma unroll
    for (int e = 0; e < 3; e++) {
        float mm = fmaxf(sc[e][0], fmaxf(sc[e][1], sc[e][2]));
        float x0 = __expf(sc[e][0] - mm);
        float x1 = __expf(sc[e][1] - mm);
        float x2 = __expf(sc[e][2] - mm);
        float inv = 1.f / (x0 + x1 + x2);
        float a0 = x0 * inv, a1 = x1 * inv, a2 = x2 * inv;
        float4 o;
        o.x = a0 * feat[0].x + a1 * feat[1].x + a2 * feat[2].x;
        o.y = a0 * feat[0].y + a1 * feat[1].y + a2 * feat[2].y;
        o.z = a0 * feat[0].z + a1 * feat[1].z + a2 * feat[2].z;
        o.w = a0 * feat[0].w + a1 * feat[1].w + a2 * feat[2].w;
        *(float4*)(dout + (size_t)(e * NN + n) * 128 + lane * 4) = o;
    }
}

// ======================= launch =======================
extern "C" void kernel_launch(void* const* d_in, const int* in_sizes, int n_in,
                              void* d_out, int out_size)
{
    const float* x          = (const float*)d_in[0];
    const float* rel_emb    = (const float*)d_in[1];
    const int*   src        = (const int*)d_in[2];
    const int*   dst        = (const int*)d_in[3];
    const float* Wn         = (const float*)d_in[4];
    const float* bn         = (const float*)d_in[5];
    const float* Wr         = (const float*)d_in[6];
    const float* br         = (const float*)d_in[7];
    const float* rel_attn_w = (const float*)d_in[8];
    const float* Wp         = (const float*)d_in[9];
    const float* bp         = (const float*)d_in[10];
    const float* Wres       = (const float*)d_in[11];
    const float* bres       = (const float*)d_in[12];
    const float* res_w      = (const float*)d_in[13];
    const float* cross_w    = (const float*)d_in[14];
    float* out = (float*)d_out;

    const int smem_bytes = SMEM_FLOATS * sizeof(float);
    cudaFuncSetAttribute(gemm_kernel, cudaFuncAttributeMaxDynamicSharedMemorySize, smem_bytes);

    prep_kernel<<<dim3(9, 3), 256>>>(rel_emb, Wn, bn, Wr, br, rel_attn_w, Wp, bp,
                                     out + RELOUT_OFF);
    zero_cnt_kernel<<<(RR * NN + 255) / 256, 256>>>();
    hist_kernel<<<(RR * EE + 255) / 256, 256>>>(dst);
    scan_kernel<<<3, 1024>>>();
    scatter_kernel<<<(RR * EE + 255) / 256, 256>>>(dst);
    gemm_kernel<<<dim3((NN + 127) / 128, 3), 256, smem_bytes>>>(x, Wn, bn, Wres, bres, out);
    agg_cross_kernel<<<(NN + 7) / 8, 256>>>(src, res_w, cross_w, out);
}